// round 1
// baseline (speedup 1.0000x reference)
#include <cuda_runtime.h>
#include <cuda_bf16.h>
#include <math_constants.h>

// ---------------------------------------------------------------------------
// HierCondLogSoftmax
//   scores      : [B, E] fp32, children of each internal node stored
//                 contiguously (flat_index = node*MAXC + child_pos).
//   out         : [B, num_nodes] fp32 ; out[b][child_index[e]] =
//                 scores[b][e] - logsumexp over e's group ; out[b][0] = 0.
//   Group = contiguous run of <= MAXC (=16) elements.
// Strategy: per-node start offsets precomputed into __device__ scratch,
// then one thread per (node, batch) does the whole group in registers.
// ---------------------------------------------------------------------------

#define MAXC 16                 // max_num_children in this dataset
#define NODE_CAP 32768          // scratch capacity (>= num_internal)

__device__ int g_start[NODE_CAP + 1];
__device__ int g_num_internal;

// Pass 1: derive group start offsets from flat_index.
__global__ void build_starts_kernel(const int* __restrict__ flat_index,
                                    int E,
                                    const int* __restrict__ num_internal_ptr,
                                    const int* __restrict__ max_children_ptr)
{
    int e = blockIdx.x * blockDim.x + threadIdx.x;
    if (e == 0) {
        int ni = *num_internal_ptr;
        g_num_internal = ni;
        if (ni >= 0 && ni <= NODE_CAP) g_start[ni] = E;  // sentinel end
    }
    if (e < E) {
        int fi = flat_index[e];
        int mc = *max_children_ptr;
        int node  = fi / mc;
        int child = fi - node * mc;
        if (child == 0 && node <= NODE_CAP) g_start[node] = e;
    }
}

// Pass 2: grouped log-softmax. One thread per (node, batch-row).
__global__ void __launch_bounds__(128)
hier_logsoftmax_kernel(const float* __restrict__ scores,
                       const int*   __restrict__ child_index,
                       float*       __restrict__ out,
                       int E, int num_nodes)
{
    const int n = blockIdx.x * blockDim.x + threadIdx.x;   // internal node id
    const int b = blockIdx.y;                              // batch row

    const float* __restrict__ srow = scores + (size_t)b * (size_t)E;
    float*       __restrict__ orow = out    + (size_t)b * (size_t)num_nodes;

    // Root (index 0) is the only out slot not covered by child_index here.
    if (blockIdx.x == 0 && threadIdx.x == 0) orow[0] = 0.0f;

    if (n >= g_num_internal) return;

    const int s0 = g_start[n];
    const int s1 = g_start[n + 1];
    const int c  = s1 - s0;       // 1..MAXC real children

    // Load group into registers (predicated, fully unrolled -> no local mem).
    float v[MAXC];
#pragma unroll
    for (int j = 0; j < MAXC; ++j)
        v[j] = (j < c) ? __ldg(srow + s0 + j) : -CUDART_INF_F;

    // max
    float m = v[0];
#pragma unroll
    for (int j = 1; j < MAXC; ++j) m = fmaxf(m, v[j]);

    // sum of exp  (exp(-inf - m) = 0 for padding lanes)
    float sum = 0.0f;
#pragma unroll
    for (int j = 0; j < MAXC; ++j) sum += __expf(v[j] - m);

    const float lse = m + __logf(sum);

    // Scatter results (contiguous in this dataset -> coalesced).
#pragma unroll
    for (int j = 0; j < MAXC; ++j)
        if (j < c) orow[__ldg(child_index + s0 + j)] = v[j] - lse;
}

extern "C" void kernel_launch(void* const* d_in, const int* in_sizes, int n_in,
                              void* d_out, int out_size)
{
    const float* scores      = (const float*)d_in[0];
    const int*   flat_index  = (const int*)  d_in[1];
    const int*   child_index = (const int*)  d_in[2];
    const int*   num_internal_ptr = (const int*)d_in[3];
    const int*   max_children_ptr = (const int*)d_in[4];

    const int E = in_sizes[1];                 // number of real child slots
    const int B = in_sizes[0] / E;             // batch
    const int num_nodes = out_size / B;        // E + 1

    // Pass 1: group starts.
    {
        int threads = 256;
        int blocks  = (E + threads - 1) / threads;
        build_starts_kernel<<<blocks, threads>>>(flat_index, E,
                                                 num_internal_ptr,
                                                 max_children_ptr);
    }

    // Pass 2: node-count upper bound. Every internal node has >= 2 children
    // by construction, so num_internal <= E/2. Device-side guard uses the
    // exact g_num_internal.
    {
        const int node_bound = E / 2 + 1;
        dim3 block(128, 1, 1);
        dim3 grid((node_bound + 127) / 128, B, 1);
        hier_logsoftmax_kernel<<<grid, block>>>(scores, child_index,
                                                (float*)d_out, E, num_nodes);
    }
}